// round 15
// baseline (speedup 1.0000x reference)
#include <cuda_runtime.h>
#include <math.h>

// Two full-size intermediates (134 MB each) to break pipeline aliasing.
#define SCRATCH_ELEMS (2ull * 4096ull * 4096ull)
__device__ float g_scratch1[SCRATCH_ELEMS];
__device__ float g_scratch2[SCRATCH_ELEMS];

#define NN 4096
#define HH 2048

__device__ __forceinline__ float2 cadd(float2 a, float2 b){ return make_float2(a.x+b.x, a.y+b.y); }
__device__ __forceinline__ float2 csub(float2 a, float2 b){ return make_float2(a.x-b.x, a.y-b.y); }
__device__ __forceinline__ float2 cmul(float2 a, float2 b){
    return make_float2(fmaf(a.x, b.x, -a.y*b.y), fmaf(a.x, b.y, a.y*b.x));
}
__device__ __forceinline__ float2 mulip(float2 a){ return make_float2(-a.y, a.x); }  // * (+i)

// Pad one float2 every 16.
#define PIDX(a) ((a) + ((a) >> 4))
#define PBUF (HH + (HH >> 4))   // 2176 float2

// ---- 16-point inverse DFT in registers ----
__device__ __forceinline__ void r16_bfly(float2 g[16]) {
    const float C8 = 0.70710678118654752f;
    const float2 W1 = make_float2( 0.92387953251128674f,  0.38268343236508978f);
    const float2 W2 = make_float2( C8,  C8);
    const float2 W3 = make_float2( 0.38268343236508978f,  0.92387953251128674f);
    const float2 W6 = make_float2(-C8,  C8);
    const float2 W9 = make_float2(-0.92387953251128674f, -0.38268343236508978f);
    float2 c[16];
#pragma unroll
    for (int t0 = 0; t0 < 4; t0++) {
        float2 x0 = g[t0], x1 = g[t0+4], x2 = g[t0+8], x3 = g[t0+12];
        float2 s02 = cadd(x0,x2), d02 = csub(x0,x2);
        float2 s13 = cadd(x1,x3), d13 = csub(x1,x3);
        float2 id13 = mulip(d13);
        c[t0*4+0] = cadd(s02,s13);
        c[t0*4+1] = cadd(d02,id13);
        c[t0*4+2] = csub(s02,s13);
        c[t0*4+3] = csub(d02,id13);
    }
    c[5]  = cmul(c[5],  W1);
    c[6]  = cmul(c[6],  W2);
    c[7]  = cmul(c[7],  W3);
    c[9]  = cmul(c[9],  W2);
    c[10] = mulip(c[10]);
    c[11] = cmul(c[11], W6);
    c[13] = cmul(c[13], W3);
    c[14] = cmul(c[14], W6);
    c[15] = cmul(c[15], W9);
#pragma unroll
    for (int u0 = 0; u0 < 4; u0++) {
        float2 x0 = c[u0], x1 = c[4+u0], x2 = c[8+u0], x3 = c[12+u0];
        float2 s02 = cadd(x0,x2), d02 = csub(x0,x2);
        float2 s13 = cadd(x1,x3), d13 = csub(x1,x3);
        float2 id13 = mulip(d13);
        g[u0]    = cadd(s02,s13);
        g[u0+4]  = cadd(d02,id13);
        g[u0+8]  = csub(s02,s13);
        g[u0+12] = csub(d02,id13);
    }
}

// ---- 8-point inverse DFT in registers ----
__device__ __forceinline__ void r8_bfly(float2 a[8]) {
    const float C8 = 0.70710678118654752f;
    float2 e0 = cadd(a[0],a[4]), e1 = cadd(a[1],a[5]);
    float2 e2 = cadd(a[2],a[6]), e3 = cadd(a[3],a[7]);
    float2 o0 = csub(a[0],a[4]), o1 = csub(a[1],a[5]);
    float2 o2 = csub(a[2],a[6]), o3 = csub(a[3],a[7]);
    o1 = make_float2(C8*(o1.x - o1.y),  C8*(o1.x + o1.y));
    o2 = mulip(o2);
    o3 = make_float2(-C8*(o3.x + o3.y), C8*(o3.x - o3.y));
    float2 t0 = cadd(e0,e2), t1 = csub(e0,e2);
    float2 t2 = cadd(e1,e3), t3 = csub(e1,e3);
    float2 it3 = mulip(t3);
    float2 u0 = cadd(o0,o2), u1 = csub(o0,o2);
    float2 u2 = cadd(o1,o3), u3 = csub(o1,o3);
    float2 iu3 = mulip(u3);
    a[0] = cadd(t0,t2);  a[4] = csub(t0,t2);
    a[2] = cadd(t1,it3); a[6] = csub(t1,it3);
    a[1] = cadd(u0,u2);  a[5] = csub(u0,u2);
    a[3] = cadd(u1,iu3); a[7] = csub(u1,iu3);
}

// ---------------------------------------------------------------------------
// Row FFT kernel: prologue reads DIRECTLY from global (no smem staging;
// forward/reverse lane-contiguous streams, each line touched twice -> L1 hit)
// -> radix 16/16/8 Stockham -> de-interleave epilogue. 128 thr, 1 row/CTA.
// MODE 0 = IDCT-II inverse, MODE 1 = IDXST. Safe for row-wise in-place use
// (all global loads complete before any global store).
// ---------------------------------------------------------------------------
template <int MODE>
__global__ __launch_bounds__(128, 4)
void dct_fft_kernel(const float* __restrict__ in,
                    const float2* __restrict__ expk,
                    float* __restrict__ out) {
    __shared__ __align__(16) float2 sX[PBUF];
    __shared__ __align__(16) float2 sY[PBUF];

    const int idx = threadIdx.x;
    const size_t base = (size_t)blockIdx.x * (size_t)NN;
    const float* __restrict__ gx = in + base;

    // Stage A: prologue (direct global reads) + radix-16 + twiddle, write sY.
    {
        float2 g[16];
        const float2 E32 = make_float2(0.98078528040323044f, 0.19509032201612827f);
        float sn, cs;
        __sincosf((float)(2.0*M_PI/4096.0) * (float)idx, &sn, &cs);
        float2 w = make_float2(cs, sn);
#pragma unroll
        for (int t = 0; t < 16; t++) {
            const int j = idx + 128*t;
            float Xa0, Xb0, Xa1, Xb1;
            if (MODE == 0) {
                Xa0 = gx[j];
                Xb0 = (j == 0) ? 0.0f : gx[NN - j];
                Xa1 = gx[j + HH];
                Xb1 = gx[(j == 0) ? HH : (HH - j)];
            } else {
                Xa0 = (j == 0) ? 0.0f : gx[NN - j];
                Xb0 = (j == 0) ? 0.0f : gx[j];
                Xa1 = gx[(j == 0) ? HH : (HH - j)];
                Xb1 = gx[j + HH];
            }
            const float2 ea = expk[j];
            const float2 eb = expk[j + HH];
            float2 V0 = make_float2(0.5f*(Xa0*ea.x + Xb0*ea.y),
                                    0.5f*(Xa0*ea.y - Xb0*ea.x));
            float2 V1 = make_float2(0.5f*(Xa1*eb.x + Xb1*eb.y),
                                    0.5f*(Xa1*eb.y - Xb1*eb.x));
            float2 S = cadd(V0, V1);
            float2 D = csub(V0, V1);
            float2 wd = cmul(w, D);
            g[t] = make_float2(S.x - wd.y, S.y + wd.x);
            w = cmul(w, E32);
        }
        r16_bfly(g);
        __sincosf((float)(2.0*M_PI/2048.0) * (float)idx, &sn, &cs);
        const float2 w1 = make_float2(cs, sn);
        sY[PIDX(16*idx)] = g[0];
        float2 wu = w1;
#pragma unroll
        for (int u = 1; u < 16; u++) {
            sY[PIDX(16*idx + u)] = cmul(g[u], wu);
            wu = cmul(wu, w1);
        }
    }
    __syncthreads();

    // Stage B: radix-16, S=16. Read sY, write sX.
    {
        float2 g[16];
#pragma unroll
        for (int t = 0; t < 16; t++) g[t] = sY[PIDX(idx + 128*t)];
        r16_bfly(g);
        const int p = idx >> 4, j = idx & 15;
        float sn, cs;
        __sincosf((float)(2.0*M_PI/128.0) * (float)p, &sn, &cs);
        const float2 w1 = make_float2(cs, sn);
        const int ob = j + 256*p;
        sX[PIDX(ob)] = g[0];
        float2 wu = w1;
#pragma unroll
        for (int u = 1; u < 16; u++) {
            sX[PIDX(ob + 16*u)] = cmul(g[u], wu);
            wu = cmul(wu, w1);
        }
    }
    __syncthreads();

    // Stage C: radix-8, S=256, fused with epilogue.
    {
        const int b1 = idx, b2 = 255 - idx;
        float2 A[8], Bv[8];
#pragma unroll
        for (int u = 0; u < 8; u++) A[u]  = sX[PIDX(b1 + 256*u)];
#pragma unroll
        for (int u = 0; u < 8; u++) Bv[u] = sX[PIDX(b2 + 256*u)];
        r8_bfly(A);
        r8_bfly(Bv);
        const float sgn = (MODE == 1) ? -1.0f : 1.0f;
        float4* out4 = (float4*)(out + base);
#pragma unroll
        for (int u = 0; u < 4; u++) {
            float2 z1 = A[u], z2 = Bv[7-u];
            out4[b1 + 256*u] = make_float4(z1.x, sgn*z2.y, z1.y, sgn*z2.x);
            z1 = Bv[u]; z2 = A[7-u];
            out4[b2 + 256*u] = make_float4(z1.x, sgn*z2.y, z1.y, sgn*z2.x);
        }
    }
}

// ---------------------------------------------------------------------------
// Chunked transpose R x C -> C x R: 64x64 tiles, 256 threads, float4,
// with tile-origin offsets for pipelined chunking.
// ---------------------------------------------------------------------------
__global__ __launch_bounds__(256)
void transpose_kernel(const float* __restrict__ in, float* __restrict__ out,
                      int R, int C, int c0_base, int r0_base) {
    __shared__ float tile[64][65];
    const int tx = threadIdx.x & 15;
    const int ty = threadIdx.x >> 4;
    const int c0 = c0_base + blockIdx.x * 64;
    const int r0 = r0_base + blockIdx.y * 64;

#pragma unroll
    for (int k = 0; k < 4; k++) {
        const int r = ty + 16*k;
        const float4 v = *(const float4*)(in + (size_t)(r0 + r)*C + (c0 + 4*tx));
        tile[r][4*tx+0] = v.x;
        tile[r][4*tx+1] = v.y;
        tile[r][4*tx+2] = v.z;
        tile[r][4*tx+3] = v.w;
    }
    __syncthreads();
#pragma unroll
    for (int k = 0; k < 4; k++) {
        const int r = ty + 16*k;
        float4 v;
        v.x = tile[4*tx+0][r];
        v.y = tile[4*tx+1][r];
        v.z = tile[4*tx+2][r];
        v.w = tile[4*tx+3][r];
        *(float4*)(out + (size_t)(c0 + r)*R + (r0 + 4*tx)) = v;
    }
}

// One-time host resources (handles only; launched work is identical per call).
static cudaStream_t g_s1, g_s2;
static cudaEvent_t  g_e_f10, g_e_f11, g_e_s2;
static bool         g_init_done = false;

static void ensure_init() {
    if (!g_init_done) {
        cudaStreamCreateWithFlags(&g_s1, cudaStreamNonBlocking);
        cudaStreamCreateWithFlags(&g_s2, cudaStreamNonBlocking);
        cudaEventCreateWithFlags(&g_e_f10, cudaEventDisableTiming);
        cudaEventCreateWithFlags(&g_e_f11, cudaEventDisableTiming);
        cudaEventCreateWithFlags(&g_e_s2,  cudaEventDisableTiming);
        g_init_done = true;
    }
}

extern "C" void kernel_launch(void* const* d_in, const int* in_sizes, int n_in,
                              void* d_out, int out_size) {
    const float*  x     = (const float*)d_in[0];
    const float2* expkM = (const float2*)d_in[1];
    const float2* expkN = (const float2*)d_in[2];
    const int M = in_sizes[1] / 2;            // 4096
    const int N = in_sizes[2] / 2;            // 4096
    float* out = (float*)d_out;

    ensure_init();

    float *scr1 = nullptr, *scr2 = nullptr;
    cudaGetSymbolAddress((void**)&scr1, g_scratch1);
    cudaGetSymbolAddress((void**)&scr2, g_scratch2);

    const size_t be = (size_t)M * (size_t)N;   // elements per batch
    const int HC = 2048;                       // chunk size along N
    dim3 tblk(256);
    dim3 t1grid(HC/64, M/64);                  // T1 chunk: 32 x 64 tiles
    dim3 t2grid(M/64, HC/64);                  // T2 chunk: 64 x 32 tiles

    // Chain per (b, x):  F1(b) -> T1h(b,x) -> F2h(b,x, in-place scr2) -> T2h(b,x -> d_out)
    // s0: chains (0,0), (1,0). s1: F1(1). s2: chains (0,1), (1,1).

    // ---- s0: F1(0) ----
    dct_fft_kernel<1><<<M, 128, 0, 0>>>(x, expkN, scr1);
    cudaEventRecord(g_e_f10, 0);

    // ---- s1: F1(1) ----
    cudaStreamWaitEvent(g_s1, g_e_f10, 0);
    dct_fft_kernel<1><<<M, 128, 0, g_s1>>>(x + be, expkN, scr1 + be);
    cudaEventRecord(g_e_f11, g_s1);

    // ---- s2: chunk-1 chains ----
    cudaStreamWaitEvent(g_s2, g_e_f10, 0);
    // (0,1)
    transpose_kernel<<<t1grid, tblk, 0, g_s2>>>(scr1, scr2, M, N, HC, 0);
    dct_fft_kernel<0><<<HC, 128, 0, g_s2>>>(scr2 + (size_t)HC*NN, expkM,
                                            scr2 + (size_t)HC*NN);
    transpose_kernel<<<t2grid, tblk, 0, g_s2>>>(scr2, out, N, M, 0, HC);
    // (1,1)
    cudaStreamWaitEvent(g_s2, g_e_f11, 0);
    transpose_kernel<<<t1grid, tblk, 0, g_s2>>>(scr1 + be, scr2 + be, M, N, HC, 0);
    dct_fft_kernel<0><<<HC, 128, 0, g_s2>>>(scr2 + be + (size_t)HC*NN, expkM,
                                            scr2 + be + (size_t)HC*NN);
    transpose_kernel<<<t2grid, tblk, 0, g_s2>>>(scr2 + be, out + be, N, M, 0, HC);
    cudaEventRecord(g_e_s2, g_s2);

    // ---- s0: chunk-0 chains ----
    // (0,0)
    transpose_kernel<<<t1grid, tblk, 0, 0>>>(scr1, scr2, M, N, 0, 0);
    dct_fft_kernel<0><<<HC, 128, 0, 0>>>(scr2, expkM, scr2);
    transpose_kernel<<<t2grid, tblk, 0, 0>>>(scr2, out, N, M, 0, 0);
    // (1,0)
    cudaStreamWaitEvent(0, g_e_f11, 0);
    transpose_kernel<<<t1grid, tblk, 0, 0>>>(scr1 + be, scr2 + be, M, N, 0, 0);
    dct_fft_kernel<0><<<HC, 128, 0, 0>>>(scr2 + be, expkM, scr2 + be);
    transpose_kernel<<<t2grid, tblk, 0, 0>>>(scr2 + be, out + be, N, M, 0, 0);

    // ---- join ----
    cudaStreamWaitEvent(0, g_e_s2, 0);
}

// round 16
// speedup vs baseline: 1.0132x; 1.0132x over previous
#include <cuda_runtime.h>
#include <math.h>

// Two full-size intermediates (134 MB each) to break pipeline aliasing.
#define SCRATCH_ELEMS (2ull * 4096ull * 4096ull)
__device__ float g_scratch1[SCRATCH_ELEMS];
__device__ float g_scratch2[SCRATCH_ELEMS];

#define NN 4096
#define HH 2048

__device__ __forceinline__ float2 cadd(float2 a, float2 b){ return make_float2(a.x+b.x, a.y+b.y); }
__device__ __forceinline__ float2 csub(float2 a, float2 b){ return make_float2(a.x-b.x, a.y-b.y); }
__device__ __forceinline__ float2 cmul(float2 a, float2 b){
    return make_float2(fmaf(a.x, b.x, -a.y*b.y), fmaf(a.x, b.y, a.y*b.x));
}
__device__ __forceinline__ float2 mulip(float2 a){ return make_float2(-a.y, a.x); }  // * (+i)

// Pad one float2 every 16.
#define PIDX(a) ((a) + ((a) >> 4))
#define PBUF (HH + (HH >> 4))   // 2176 float2

// ---- 16-point inverse DFT in registers ----
__device__ __forceinline__ void r16_bfly(float2 g[16]) {
    const float C8 = 0.70710678118654752f;
    const float2 W1 = make_float2( 0.92387953251128674f,  0.38268343236508978f);
    const float2 W2 = make_float2( C8,  C8);
    const float2 W3 = make_float2( 0.38268343236508978f,  0.92387953251128674f);
    const float2 W6 = make_float2(-C8,  C8);
    const float2 W9 = make_float2(-0.92387953251128674f, -0.38268343236508978f);
    float2 c[16];
#pragma unroll
    for (int t0 = 0; t0 < 4; t0++) {
        float2 x0 = g[t0], x1 = g[t0+4], x2 = g[t0+8], x3 = g[t0+12];
        float2 s02 = cadd(x0,x2), d02 = csub(x0,x2);
        float2 s13 = cadd(x1,x3), d13 = csub(x1,x3);
        float2 id13 = mulip(d13);
        c[t0*4+0] = cadd(s02,s13);
        c[t0*4+1] = cadd(d02,id13);
        c[t0*4+2] = csub(s02,s13);
        c[t0*4+3] = csub(d02,id13);
    }
    c[5]  = cmul(c[5],  W1);
    c[6]  = cmul(c[6],  W2);
    c[7]  = cmul(c[7],  W3);
    c[9]  = cmul(c[9],  W2);
    c[10] = mulip(c[10]);
    c[11] = cmul(c[11], W6);
    c[13] = cmul(c[13], W3);
    c[14] = cmul(c[14], W6);
    c[15] = cmul(c[15], W9);
#pragma unroll
    for (int u0 = 0; u0 < 4; u0++) {
        float2 x0 = c[u0], x1 = c[4+u0], x2 = c[8+u0], x3 = c[12+u0];
        float2 s02 = cadd(x0,x2), d02 = csub(x0,x2);
        float2 s13 = cadd(x1,x3), d13 = csub(x1,x3);
        float2 id13 = mulip(d13);
        g[u0]    = cadd(s02,s13);
        g[u0+4]  = cadd(d02,id13);
        g[u0+8]  = csub(s02,s13);
        g[u0+12] = csub(d02,id13);
    }
}

// ---- 8-point inverse DFT in registers ----
__device__ __forceinline__ void r8_bfly(float2 a[8]) {
    const float C8 = 0.70710678118654752f;
    float2 e0 = cadd(a[0],a[4]), e1 = cadd(a[1],a[5]);
    float2 e2 = cadd(a[2],a[6]), e3 = cadd(a[3],a[7]);
    float2 o0 = csub(a[0],a[4]), o1 = csub(a[1],a[5]);
    float2 o2 = csub(a[2],a[6]), o3 = csub(a[3],a[7]);
    o1 = make_float2(C8*(o1.x - o1.y),  C8*(o1.x + o1.y));
    o2 = mulip(o2);
    o3 = make_float2(-C8*(o3.x + o3.y), C8*(o3.x - o3.y));
    float2 t0 = cadd(e0,e2), t1 = csub(e0,e2);
    float2 t2 = cadd(e1,e3), t3 = csub(e1,e3);
    float2 it3 = mulip(t3);
    float2 u0 = cadd(o0,o2), u1 = csub(o0,o2);
    float2 u2 = cadd(o1,o3), u3 = csub(o1,o3);
    float2 iu3 = mulip(u3);
    a[0] = cadd(t0,t2);  a[4] = csub(t0,t2);
    a[2] = cadd(t1,it3); a[6] = csub(t1,it3);
    a[1] = cadd(u0,u2);  a[5] = csub(u0,u2);
    a[3] = cadd(u1,iu3); a[7] = csub(u1,iu3);
}

// ---------------------------------------------------------------------------
// Row FFT kernel (round-14 proven, smem staging): 128 thr, 1 row/CTA,
// radix 16/16/8. MODE 0 = IDCT-II inverse, MODE 1 = IDXST.
// Safe for row-wise in-place use.
// ---------------------------------------------------------------------------
template <int MODE>
__global__ __launch_bounds__(128, 4)
void dct_fft_kernel(const float* __restrict__ in,
                    const float2* __restrict__ expk,
                    float* __restrict__ out) {
    __shared__ __align__(16) float2 sX[PBUF];
    __shared__ __align__(16) float2 sY[PBUF];
    float* xs = (float*)sX;

    const int idx = threadIdx.x;
    const size_t base = (size_t)blockIdx.x * (size_t)NN;

    {
        const float4* in4 = (const float4*)(in + base);
        float4* xs4 = (float4*)xs;
#pragma unroll
        for (int i = idx; i < NN/4; i += 128) xs4[i] = in4[i];
    }
    __syncthreads();

    {
        float2 g[16];
        const float2 E32 = make_float2(0.98078528040323044f, 0.19509032201612827f);
        float sn, cs;
        __sincosf((float)(2.0*M_PI/4096.0) * (float)idx, &sn, &cs);
        float2 w = make_float2(cs, sn);
#pragma unroll
        for (int t = 0; t < 16; t++) {
            const int j = idx + 128*t;
            float Xa0, Xb0, Xa1, Xb1;
            if (MODE == 0) {
                Xa0 = xs[j];
                Xb0 = (j == 0) ? 0.0f : xs[NN - j];
                Xa1 = xs[j + HH];
                Xb1 = xs[(j == 0) ? HH : (HH - j)];
            } else {
                Xa0 = (j == 0) ? 0.0f : xs[NN - j];
                Xb0 = (j == 0) ? 0.0f : xs[j];
                Xa1 = xs[(j == 0) ? HH : (HH - j)];
                Xb1 = xs[j + HH];
            }
            const float2 ea = expk[j];
            const float2 eb = expk[j + HH];
            float2 V0 = make_float2(0.5f*(Xa0*ea.x + Xb0*ea.y),
                                    0.5f*(Xa0*ea.y - Xb0*ea.x));
            float2 V1 = make_float2(0.5f*(Xa1*eb.x + Xb1*eb.y),
                                    0.5f*(Xa1*eb.y - Xb1*eb.x));
            float2 S = cadd(V0, V1);
            float2 D = csub(V0, V1);
            float2 wd = cmul(w, D);
            g[t] = make_float2(S.x - wd.y, S.y + wd.x);
            w = cmul(w, E32);
        }
        r16_bfly(g);
        __sincosf((float)(2.0*M_PI/2048.0) * (float)idx, &sn, &cs);
        const float2 w1 = make_float2(cs, sn);
        sY[PIDX(16*idx)] = g[0];
        float2 wu = w1;
#pragma unroll
        for (int u = 1; u < 16; u++) {
            sY[PIDX(16*idx + u)] = cmul(g[u], wu);
            wu = cmul(wu, w1);
        }
    }
    __syncthreads();

    {
        float2 g[16];
#pragma unroll
        for (int t = 0; t < 16; t++) g[t] = sY[PIDX(idx + 128*t)];
        r16_bfly(g);
        const int p = idx >> 4, j = idx & 15;
        float sn, cs;
        __sincosf((float)(2.0*M_PI/128.0) * (float)p, &sn, &cs);
        const float2 w1 = make_float2(cs, sn);
        const int ob = j + 256*p;
        sX[PIDX(ob)] = g[0];
        float2 wu = w1;
#pragma unroll
        for (int u = 1; u < 16; u++) {
            sX[PIDX(ob + 16*u)] = cmul(g[u], wu);
            wu = cmul(wu, w1);
        }
    }
    __syncthreads();

    {
        const int b1 = idx, b2 = 255 - idx;
        float2 A[8], Bv[8];
#pragma unroll
        for (int u = 0; u < 8; u++) A[u]  = sX[PIDX(b1 + 256*u)];
#pragma unroll
        for (int u = 0; u < 8; u++) Bv[u] = sX[PIDX(b2 + 256*u)];
        r8_bfly(A);
        r8_bfly(Bv);
        const float sgn = (MODE == 1) ? -1.0f : 1.0f;
        float4* out4 = (float4*)(out + base);
#pragma unroll
        for (int u = 0; u < 4; u++) {
            float2 z1 = A[u], z2 = Bv[7-u];
            out4[b1 + 256*u] = make_float4(z1.x, sgn*z2.y, z1.y, sgn*z2.x);
            z1 = Bv[u]; z2 = A[7-u];
            out4[b2 + 256*u] = make_float4(z1.x, sgn*z2.y, z1.y, sgn*z2.x);
        }
    }
}

// ---------------------------------------------------------------------------
// Chunked transpose (4096x4096): 64x64 tiles, 256 threads, float4,
// with tile-origin offsets for pipelined chunking.
// ---------------------------------------------------------------------------
__global__ __launch_bounds__(256)
void transpose_kernel(const float* __restrict__ in, float* __restrict__ out,
                      int R, int C, int c0_base, int r0_base) {
    __shared__ float tile[64][65];
    const int tx = threadIdx.x & 15;
    const int ty = threadIdx.x >> 4;
    const int c0 = c0_base + blockIdx.x * 64;
    const int r0 = r0_base + blockIdx.y * 64;

#pragma unroll
    for (int k = 0; k < 4; k++) {
        const int r = ty + 16*k;
        const float4 v = *(const float4*)(in + (size_t)(r0 + r)*C + (c0 + 4*tx));
        tile[r][4*tx+0] = v.x;
        tile[r][4*tx+1] = v.y;
        tile[r][4*tx+2] = v.z;
        tile[r][4*tx+3] = v.w;
    }
    __syncthreads();
#pragma unroll
    for (int k = 0; k < 4; k++) {
        const int r = ty + 16*k;
        float4 v;
        v.x = tile[4*tx+0][r];
        v.y = tile[4*tx+1][r];
        v.z = tile[4*tx+2][r];
        v.w = tile[4*tx+3][r];
        *(float4*)(out + (size_t)(c0 + r)*R + (r0 + 4*tx)) = v;
    }
}

// One-time host resources (handles only; launched work is identical per call).
static cudaStream_t g_s1, g_s2;
static cudaEvent_t  g_e00, g_e01, g_e10, g_e11, g_es2;
static bool         g_init_done = false;

static void ensure_init() {
    if (!g_init_done) {
        cudaStreamCreateWithFlags(&g_s1, cudaStreamNonBlocking);
        cudaStreamCreateWithFlags(&g_s2, cudaStreamNonBlocking);
        cudaEventCreateWithFlags(&g_e00, cudaEventDisableTiming);
        cudaEventCreateWithFlags(&g_e01, cudaEventDisableTiming);
        cudaEventCreateWithFlags(&g_e10, cudaEventDisableTiming);
        cudaEventCreateWithFlags(&g_e11, cudaEventDisableTiming);
        cudaEventCreateWithFlags(&g_es2, cudaEventDisableTiming);
        g_init_done = true;
    }
}

extern "C" void kernel_launch(void* const* d_in, const int* in_sizes, int n_in,
                              void* d_out, int out_size) {
    const float*  x     = (const float*)d_in[0];
    const float2* expkM = (const float2*)d_in[1];
    const float2* expkN = (const float2*)d_in[2];
    float* out = (float*)d_out;

    ensure_init();

    float *scr1 = nullptr, *scr2 = nullptr;
    cudaGetSymbolAddress((void**)&scr1, g_scratch1);
    cudaGetSymbolAddress((void**)&scr2, g_scratch2);

    const size_t be = (size_t)NN * (size_t)NN;     // elements per batch
    const size_t hrows = (size_t)HH * (size_t)NN;  // 2048 rows of floats
    dim3 tblk(256);
    dim3 t1grid(32, 32);                           // 2048 cols x 2048 rows
    dim3 t2grid(64, 32);                           // 4096 cols x 2048 rows

    // F1(b,h): IDXST on rows [h*2048, h*2048+2048) of batch b: x -> scr1
    // T1(b,h,x): quarter transpose scr1 -> scr2 (cols chunk x, rows half h)
    // F2(b,x): IDCT in-place on scr2 rows [x*2048, +2048) (needs both halves)
    // T2(b,x): half transpose scr2 rows chunk x -> d_out

    // ---- s0 head: F1(0,0) ----
    dct_fft_kernel<1><<<HH, 128, 0, 0>>>(x, expkN, scr1);
    cudaEventRecord(g_e00, 0);

    // ---- s1: remaining three F1 launches ----
    cudaStreamWaitEvent(g_s1, g_e00, 0);
    dct_fft_kernel<1><<<HH, 128, 0, g_s1>>>(x + hrows, expkN, scr1 + hrows);
    cudaEventRecord(g_e01, g_s1);
    dct_fft_kernel<1><<<HH, 128, 0, g_s1>>>(x + be, expkN, scr1 + be);
    cudaEventRecord(g_e10, g_s1);
    dct_fft_kernel<1><<<HH, 128, 0, g_s1>>>(x + be + hrows, expkN, scr1 + be + hrows);
    cudaEventRecord(g_e11, g_s1);

    // ---- s2: chains for chunk x=1 (both batches) ----
    cudaStreamWaitEvent(g_s2, g_e00, 0);
    transpose_kernel<<<t1grid, tblk, 0, g_s2>>>(scr1, scr2, NN, NN, HH, 0);      // T1(0,0,1)
    cudaStreamWaitEvent(g_s2, g_e01, 0);
    transpose_kernel<<<t1grid, tblk, 0, g_s2>>>(scr1, scr2, NN, NN, HH, HH);     // T1(0,1,1)
    dct_fft_kernel<0><<<HH, 128, 0, g_s2>>>(scr2 + hrows, expkM, scr2 + hrows);  // F2(0,1)
    transpose_kernel<<<t2grid, tblk, 0, g_s2>>>(scr2, out, NN, NN, 0, HH);       // T2(0,1)
    cudaStreamWaitEvent(g_s2, g_e10, 0);
    transpose_kernel<<<t1grid, tblk, 0, g_s2>>>(scr1 + be, scr2 + be, NN, NN, HH, 0);   // T1(1,0,1)
    cudaStreamWaitEvent(g_s2, g_e11, 0);
    transpose_kernel<<<t1grid, tblk, 0, g_s2>>>(scr1 + be, scr2 + be, NN, NN, HH, HH);  // T1(1,1,1)
    dct_fft_kernel<0><<<HH, 128, 0, g_s2>>>(scr2 + be + hrows, expkM, scr2 + be + hrows); // F2(1,1)
    transpose_kernel<<<t2grid, tblk, 0, g_s2>>>(scr2 + be, out + be, NN, NN, 0, HH);    // T2(1,1)
    cudaEventRecord(g_es2, g_s2);

    // ---- s0: chains for chunk x=0 (both batches) ----
    transpose_kernel<<<t1grid, tblk, 0, 0>>>(scr1, scr2, NN, NN, 0, 0);          // T1(0,0,0)
    cudaStreamWaitEvent(0, g_e01, 0);
    transpose_kernel<<<t1grid, tblk, 0, 0>>>(scr1, scr2, NN, NN, 0, HH);         // T1(0,1,0)
    dct_fft_kernel<0><<<HH, 128, 0, 0>>>(scr2, expkM, scr2);                     // F2(0,0)
    transpose_kernel<<<t2grid, tblk, 0, 0>>>(scr2, out, NN, NN, 0, 0);           // T2(0,0)
    cudaStreamWaitEvent(0, g_e10, 0);
    transpose_kernel<<<t1grid, tblk, 0, 0>>>(scr1 + be, scr2 + be, NN, NN, 0, 0);    // T1(1,0,0)
    cudaStreamWaitEvent(0, g_e11, 0);
    transpose_kernel<<<t1grid, tblk, 0, 0>>>(scr1 + be, scr2 + be, NN, NN, 0, HH);   // T1(1,1,0)
    dct_fft_kernel<0><<<HH, 128, 0, 0>>>(scr2 + be, expkM, scr2 + be);               // F2(1,0)
    transpose_kernel<<<t2grid, tblk, 0, 0>>>(scr2 + be, out + be, NN, NN, 0, 0);     // T2(1,0)

    // ---- join ----
    cudaStreamWaitEvent(0, g_es2, 0);
}